// round 16
// baseline (speedup 1.0000x reference)
#include <cuda_runtime.h>
#include <cuda_fp16.h>
#include <mma.h>
using namespace nvcuda;

#define NN 100000
#define NE 1600000
#define NG 64

// ---------------- scratch (device globals) ---------------------------------
__device__ float   g_dinv[NN];
__device__ int     g_deg[NN];
__device__ int     g_rowptr[NN];
__device__ int     g_cursor[NN];
__device__ int     g_bsum[128];
__device__ int     g_csr[NE];
__device__ __half2 g_h1p[(size_t)NN * 64];   // fp16: dinv * (x W1), 128 feat
__device__ __half2 g_h1h[(size_t)NN * 64];   // fp16: post agg+relu (gemm2 in)
__device__ __half2 g_h2p[(size_t)NN * 32];   // fp16: dinv * (h1 W2), 64 feat
__device__ float   g_gsum[NG * 64];
__device__ float   g_gcnt[NG];

__device__ __forceinline__ void red_add_v4(float* p, float4 v) {
    asm volatile("red.global.add.v4.f32 [%0], {%1, %2, %3, %4};"
                 :: "l"(p), "f"(v.x), "f"(v.y), "f"(v.z), "f"(v.w)
                 : "memory");
}
__device__ __forceinline__ float2 h2f(float raw) {
    return __half22float2(*reinterpret_cast<__half2*>(&raw));
}

// ---------------- init ------------------------------------------------------
__global__ void k_init(int n) {
    int i = blockIdx.x * blockDim.x + threadIdx.x;
    if (i < n)       g_deg[i] = 0;
    if (i < NG * 64) g_gsum[i] = 0.0f;
    if (i < NG)      g_gcnt[i] = 0.0f;
}

// ---------------- degree histogram over dst (4 edges/thread) ---------------
__global__ void k_hist(const int* __restrict__ dst, int E) {
    int i = blockIdx.x * blockDim.x + threadIdx.x;
    int e = i << 2;
    if (e + 4 <= E) {
        int4 d = __ldg((const int4*)dst + i);
        atomicAdd(&g_deg[d.x], 1);
        atomicAdd(&g_deg[d.y], 1);
        atomicAdd(&g_deg[d.z], 1);
        atomicAdd(&g_deg[d.w], 1);
    } else {
        for (; e < E; e++) atomicAdd(&g_deg[dst[e]], 1);
    }
}

// ---------------- scan step 1: per-block (1024) scan -----------------------
__global__ void k_scan1(int n) {
    __shared__ int sh[1024];
    int tid = threadIdx.x;
    int i = blockIdx.x * 1024 + tid;
    int v = (i < n) ? g_deg[i] : 0;
    sh[tid] = v;
    __syncthreads();
#pragma unroll
    for (int off = 1; off < 1024; off <<= 1) {
        int t = (tid >= off) ? sh[tid - off] : 0;
        __syncthreads();
        sh[tid] += t;
        __syncthreads();
    }
    if (i < n) g_rowptr[i] = sh[tid] - v;          // exclusive
    if (tid == 1023) g_bsum[blockIdx.x] = sh[1023];
}

// ---------------- scan step 2: warp-shuffle scan of block sums -------------
__global__ void k_scan2(int nb) {
    int lane = threadIdx.x;   // 32 threads
    int carry = 0;
    for (int base = 0; base < nb; base += 32) {
        int idx = base + lane;
        int orig = (idx < nb) ? g_bsum[idx] : 0;
        int v = orig;
#pragma unroll
        for (int off = 1; off < 32; off <<= 1) {
            int u = __shfl_up_sync(0xFFFFFFFFu, v, off);
            if (lane >= off) v += u;
        }
        if (idx < nb) g_bsum[idx] = v - orig + carry;   // exclusive + carry
        carry += __shfl_sync(0xFFFFFFFFu, v, 31);
    }
}

// ---------------- scan step 3: offsets, cursor, dinv, graph counts ---------
__global__ void k_scan3(const int* __restrict__ batch, int n) {
    int i = blockIdx.x * blockDim.x + threadIdx.x;
    if (i < n) {
        int r = g_rowptr[i] + g_bsum[i >> 10];
        g_rowptr[i] = r;
        g_cursor[i] = r;
        g_dinv[i]   = rsqrtf((float)g_deg[i] + 1.0f);   // +1 self loop
        atomicAdd(&g_gcnt[batch[i]], 1.0f);
    }
}

// ---------------- CSR scatter (4 edges/thread) -----------------------------
__global__ void k_scatter(const int* __restrict__ src,
                          const int* __restrict__ dst, int E) {
    int i = blockIdx.x * blockDim.x + threadIdx.x;
    int e = i << 2;
    if (e + 4 <= E) {
        int4 s4 = __ldg((const int4*)src + i);
        int4 d4 = __ldg((const int4*)dst + i);
        g_csr[atomicAdd(&g_cursor[d4.x], 1)] = s4.x;
        g_csr[atomicAdd(&g_cursor[d4.y], 1)] = s4.y;
        g_csr[atomicAdd(&g_cursor[d4.z], 1)] = s4.z;
        g_csr[atomicAdd(&g_cursor[d4.w], 1)] = s4.w;
    } else {
        for (; e < E; e++)
            g_csr[atomicAdd(&g_cursor[dst[e]], 1)] = src[e];
    }
}

// ---------------- TF32 GEMM + register-prefetch double buffer --------------
// LAYER 1: A = x (fp32 arg), C = g_h1p, BN = 128.
// LAYER 2: A = g_h1h (fp16),  C = g_h2p, BN = 64.
template <int LAYER>
__global__ void k_gemm(const float* __restrict__ Ain,
                       const float* __restrict__ W, int M) {
    constexpr int BN  = (LAYER == 1) ? 128 : 64;
    constexpr int K   = 128;
    constexpr int KC  = 32;
    constexpr int LDA = KC + 8;                 // 40
    constexpr int LDB = BN + 8;                 // 136 / 72
    constexpr int WN  = BN / 2;
    constexpr int NF  = WN / 16;
    constexpr int NA  = (LAYER == 1) ? 4 : 2;   // A float4 loads per thread
    constexpr int NB  = KC * BN / 4 / 256;      // B float4 loads per thread
    __half2* __restrict__ C = (LAYER == 1) ? g_h1p : g_h2p;
    constexpr int CH2 = BN / 2;

    __shared__ __align__(16) float As[128][LDA];
    __shared__ __align__(16) float Bs[KC][LDB];

    const int t    = threadIdx.x;
    const int wid  = t >> 5;
    const int lane = t & 31;
    const int mbase = blockIdx.x * 128;
    const int wm = (wid >> 1) * 32;
    const int wn = (wid & 1) * WN;

    // k0-invariant load coordinates
    int  arow[NA]; int acol[NA]; float asc[NA]; bool aval[NA];
#pragma unroll
    for (int j = 0; j < NA; j++) {
        int idx = t + j * 256;
        arow[j] = (LAYER == 1) ? (idx >> 3) : (idx >> 2);
        acol[j] = (LAYER == 1) ? ((idx & 7) << 2) : (idx & 3);
        aval[j] = (mbase + arow[j] < M);
        asc[j]  = aval[j] ? g_dinv[mbase + arow[j]] : 0.0f;
    }
    int brow[NB], bcol[NB];
#pragma unroll
    for (int j = 0; j < NB; j++) {
        int idx = t + j * 256;
        brow[j] = idx / (BN / 4);
        bcol[j] = (idx % (BN / 4)) << 2;
    }

    auto loadA = [&](int k0, float4* r) {
#pragma unroll
        for (int j = 0; j < NA; j++) {
            r[j] = make_float4(0.f, 0.f, 0.f, 0.f);
            if (aval[j]) {
                if (LAYER == 1)
                    r[j] = *reinterpret_cast<const float4*>(
                        Ain + (size_t)(mbase + arow[j]) * K + k0 + acol[j]);
                else
                    r[j] = *((const float4*)g_h1h +
                             (size_t)(mbase + arow[j]) * 16 + (k0 >> 3) + acol[j]);
            }
        }
    };
    auto storeA = [&](const float4* r) {
#pragma unroll
        for (int j = 0; j < NA; j++) {
            if (LAYER == 1) {
                int kq = acol[j];
                As[arow[j]][kq + 0] = wmma::__float_to_tf32(asc[j] * r[j].x);
                As[arow[j]][kq + 1] = wmma::__float_to_tf32(asc[j] * r[j].y);
                As[arow[j]][kq + 2] = wmma::__float_to_tf32(asc[j] * r[j].z);
                As[arow[j]][kq + 3] = wmma::__float_to_tf32(asc[j] * r[j].w);
            } else {
                int c8 = acol[j] << 3;
                float2 f0 = h2f(r[j].x), f1 = h2f(r[j].y);
                float2 f2 = h2f(r[j].z), f3 = h2f(r[j].w);
                As[arow[j]][c8 + 0] = wmma::__float_to_tf32(asc[j] * f0.x);
                As[arow[j]][c8 + 1] = wmma::__float_to_tf32(asc[j] * f0.y);
                As[arow[j]][c8 + 2] = wmma::__float_to_tf32(asc[j] * f1.x);
                As[arow[j]][c8 + 3] = wmma::__float_to_tf32(asc[j] * f1.y);
                As[arow[j]][c8 + 4] = wmma::__float_to_tf32(asc[j] * f2.x);
                As[arow[j]][c8 + 5] = wmma::__float_to_tf32(asc[j] * f2.y);
                As[arow[j]][c8 + 6] = wmma::__float_to_tf32(asc[j] * f3.x);
                As[arow[j]][c8 + 7] = wmma::__float_to_tf32(asc[j] * f3.y);
            }
        }
    };
    auto loadB = [&](int k0, float4* r) {
#pragma unroll
        for (int j = 0; j < NB; j++)
            r[j] = *reinterpret_cast<const float4*>(
                W + (size_t)(k0 + brow[j]) * BN + bcol[j]);
    };
    auto storeB = [&](const float4* r) {
#pragma unroll
        for (int j = 0; j < NB; j++) {
            Bs[brow[j]][bcol[j] + 0] = wmma::__float_to_tf32(r[j].x);
            Bs[brow[j]][bcol[j] + 1] = wmma::__float_to_tf32(r[j].y);
            Bs[brow[j]][bcol[j] + 2] = wmma::__float_to_tf32(r[j].z);
            Bs[brow[j]][bcol[j] + 3] = wmma::__float_to_tf32(r[j].w);
        }
    };

    wmma::fragment<wmma::accumulator, 16, 16, 8, float> c[2][NF];
#pragma unroll
    for (int i = 0; i < 2; i++)
#pragma unroll
        for (int j = 0; j < NF; j++) wmma::fill_fragment(c[i][j], 0.0f);

    float4 pa[NA], pb[NB];
    loadA(0, pa); loadB(0, pb);
    storeA(pa);   storeB(pb);
    __syncthreads();

    for (int k0 = 0; k0 < K; k0 += KC) {
        bool more = (k0 + KC) < K;
        if (more) { loadA(k0 + KC, pa); loadB(k0 + KC, pb); }

#pragma unroll
        for (int kk = 0; kk < KC; kk += 8) {
            wmma::fragment<wmma::matrix_a, 16, 16, 8, wmma::precision::tf32, wmma::row_major> a[2];
            wmma::fragment<wmma::matrix_b, 16, 16, 8, wmma::precision::tf32, wmma::row_major> b[NF];
#pragma unroll
            for (int i = 0; i < 2; i++)
                wmma::load_matrix_sync(a[i], &As[wm + i * 16][kk], LDA);
#pragma unroll
            for (int j = 0; j < NF; j++)
                wmma::load_matrix_sync(b[j], &Bs[kk][wn + j * 16], LDB);
#pragma unroll
            for (int i = 0; i < 2; i++)
#pragma unroll
                for (int j = 0; j < NF; j++)
                    wmma::mma_sync(c[i][j], a[i], b[j], c[i][j]);
        }
        __syncthreads();
        if (more) {
            storeA(pa); storeB(pb);
            __syncthreads();
        }
    }

    // epilogue: reuse As as per-warp stage (16x20 floats each), emit half2
    float* stg = &As[0][0] + wid * 320;
#pragma unroll
    for (int i = 0; i < 2; i++)
#pragma unroll
        for (int j = 0; j < NF; j++) {
            wmma::store_matrix_sync(stg, c[i][j], 20, wmma::mem_row_major);
            __syncwarp();
#pragma unroll
            for (int it = 0; it < 4; it++) {
                int idx = lane + it * 32;            // 0..127
                int rr  = idx >> 3;                  // 0..15
                int cp  = idx & 7;                   // half2 col pair
                int m = mbase + wm + i * 16 + rr;
                if (m < M) {
                    __half2 hv = __floats2half2_rn(stg[rr * 20 + cp * 2],
                                                   stg[rr * 20 + cp * 2 + 1]);
                    C[(size_t)m * CH2 + wn / 2 + j * 8 + cp] = hv;
                }
            }
            __syncwarp();
        }
}

// ---------------- agg layer 1 (D=128): warp/node, 2 nbrs/iter, LDG.128 -----
__global__ void k_agg1(const float* __restrict__ b1, int N) {
    int w = (blockIdx.x * blockDim.x + threadIdx.x) >> 5;
    if (w >= N) return;
    int lane = threadIdx.x & 31;
    int half = lane >> 4;                       // 0 or 1
    int l16  = lane & 15;
    const float4* H = (const float4*)g_h1p;     // 16 float4 per row (256B)

    int start = g_rowptr[w];
    int cnt   = g_deg[w];

    float acc[8];
#pragma unroll
    for (int q = 0; q < 8; q++) acc[q] = 0.0f;

    if (half == 0) {                            // self term
        float4 r = __ldg(H + (size_t)w * 16 + l16);
        float2 f0 = h2f(r.x), f1 = h2f(r.y), f2 = h2f(r.z), f3 = h2f(r.w);
        acc[0] = f0.x; acc[1] = f0.y; acc[2] = f1.x; acc[3] = f1.y;
        acc[4] = f2.x; acc[5] = f2.y; acc[6] = f3.x; acc[7] = f3.y;
    }

    int j = 0;
    for (; j + 8 <= cnt; j += 8) {              // 4 pairs in flight
        int s[4]; float4 r[4];
#pragma unroll
        for (int q = 0; q < 4; q++) s[q] = __ldg(g_csr + start + j + 2 * q + half);
#pragma unroll
        for (int q = 0; q < 4; q++) r[q] = __ldg(H + (size_t)s[q] * 16 + l16);
#pragma unroll
        for (int q = 0; q < 4; q++) {
            float2 f0 = h2f(r[q].x), f1 = h2f(r[q].y);
            float2 f2 = h2f(r[q].z), f3 = h2f(r[q].w);
            acc[0] += f0.x; acc[1] += f0.y; acc[2] += f1.x; acc[3] += f1.y;
            acc[4] += f2.x; acc[5] += f2.y; acc[6] += f3.x; acc[7] += f3.y;
        }
    }
    for (; j + 2 <= cnt; j += 2) {
        int s = __ldg(g_csr + start + j + half);
        float4 r = __ldg(H + (size_t)s * 16 + l16);
        float2 f0 = h2f(r.x), f1 = h2f(r.y), f2 = h2f(r.z), f3 = h2f(r.w);
        acc[0] += f0.x; acc[1] += f0.y; acc[2] += f1.x; acc[3] += f1.y;
        acc[4] += f2.x; acc[5] += f2.y; acc[6] += f3.x; acc[7] += f3.y;
    }
    if (j < cnt && half == 0) {                 // odd tail
        int s = __ldg(g_csr + start + j);
        float4 r = __ldg(H + (size_t)s * 16 + l16);
        float2 f0 = h2f(r.x), f1 = h2f(r.y), f2 = h2f(r.z), f3 = h2f(r.w);
        acc[0] += f0.x; acc[1] += f0.y; acc[2] += f1.x; acc[3] += f1.y;
        acc[4] += f2.x; acc[5] += f2.y; acc[6] += f3.x; acc[7] += f3.y;
    }

#pragma unroll
    for (int q = 0; q < 8; q++)
        acc[q] += __shfl_xor_sync(0xFFFFFFFFu, acc[q], 16);

    if (half == 0) {
        float di = g_dinv[w];
        float4 bb0 = __ldg((const float4*)b1 + l16 * 2);
        float4 bb1 = __ldg((const float4*)b1 + l16 * 2 + 1);
        float v0 = fmaxf(di * acc[0] + bb0.x, 0.0f);
        float v1 = fmaxf(di * acc[1] + bb0.y, 0.0f);
        float v2 = fmaxf(di * acc[2] + bb0.z, 0.0f);
        float v3 = fmaxf(di * acc[3] + bb0.w, 0.0f);
        float v4 = fmaxf(di * acc[4] + bb1.x, 0.0f);
        float v5 = fmaxf(di * acc[5] + bb1.y, 0.0f);
        float v6 = fmaxf(di * acc[6] + bb1.z, 0.0f);
        float v7 = fmaxf(di * acc[7] + bb1.w, 0.0f);
        uint4 u;
        *reinterpret_cast<__half2*>(&u.x) = __floats2half2_rn(v0, v1);
        *reinterpret_cast<__half2*>(&u.y) = __floats2half2_rn(v2, v3);
        *reinterpret_cast<__half2*>(&u.z) = __floats2half2_rn(v4, v5);
        *reinterpret_cast<__half2*>(&u.w) = __floats2half2_rn(v6, v7);
        ((uint4*)g_h1h)[(size_t)w * 16 + l16] = u;
    }
}

// ---------------- agg layer 2 (D=64)+pool: warp/node, 4 nbrs/iter, LDG.128 -
// lanes split into 4 groups of 8; group g covers neighbor j+g, 8 lanes/row.
__global__ void k_agg2(const int* __restrict__ batch,
                       const float* __restrict__ b2, int N) {
    int w = (blockIdx.x * blockDim.x + threadIdx.x) >> 5;
    if (w >= N) return;
    int lane = threadIdx.x & 31;
    int grp = lane >> 3;                        // 0..3
    int l8  = lane & 7;
    const float4* H = (const float4*)g_h2p;     // 8 float4 per row (128B)

    int start = g_rowptr[w];
    int cnt   = g_deg[w];

    float acc[8];
#pragma unroll
    for (int q = 0; q < 8; q++) acc[q] = 0.0f;

    if (grp == 0) {                             // self term
        float4 r = __ldg(H + (size_t)w * 8 + l8);
        float2 f0 = h2f(r.x), f1 = h2f(r.y), f2 = h2f(r.z), f3 = h2f(r.w);
        acc[0] = f0.x; acc[1] = f0.y; acc[2] = f1.x; acc[3] = f1.y;
        acc[4] = f2.x; acc[5] = f2.y; acc[6] = f3.x; acc[7] = f3.y;
    }

    int j = 0;
    for (; j + 8 <= cnt; j += 8) {              // 8 rows in flight (2/group)
        int s[2]; float4 r[2];
        s[0] = __ldg(g_csr + start + j + grp);
        s[1] = __ldg(g_csr + start + j + 4 + grp);
        r[0] = __ldg(H + (size_t)s[0] * 8 + l8);
        r[1] = __ldg(H + (size_t)s[1] * 8 + l8);
#pragma unroll
        for (int q = 0; q < 2; q++) {
            float2 f0 = h2f(r[q].x), f1 = h2f(r[q].y);
            float2 f2 = h2f(r[q].z), f3 = h2f(r[q].w);
            acc[0] += f0.x; acc[1] += f0.y; acc[2] += f1.x; acc[3] += f1.y;
            acc[4] += f2.x; acc[5] += f2.y; acc[6] += f3.x; acc[7] += f3.y;
        }
    }
    if (j + 4 <= cnt) {
        int s = __ldg(g_csr + start + j + grp);
        float4 r = __ldg(H + (size_t)s * 8 + l8);
        float2 f0 = h2f(r.x), f1 = h2f(r.y), f2 = h2f(r.z), f3 = h2f(r.w);
        acc[0] += f0.x; acc[1] += f0.y; acc[2] += f1.x; acc[3] += f1.y;
        acc[4] += f2.x; acc[5] += f2.y; acc[6] += f3.x; acc[7] += f3.y;
        j += 4;
    }
    if (j < cnt && grp < cnt - j) {             // tail 1..3
        int s = __ldg(g_csr + start + j + grp);
        float4 r = __ldg(H + (size_t)s * 8 + l8);
        float2 f0 = h2f(r.x), f1 = h2f(r.y), f2 = h2f(r.z), f3 = h2f(r.w);
        acc[0] += f0.x; acc[1] += f0.y; acc[2] += f1.x; acc[3] += f1.y;
        acc[4] += f2.x; acc[5] += f2.y; acc[6] += f3.x; acc[7] += f3.y;
    }

#pragma unroll
    for (int q = 0; q < 8; q++) {
        acc[q] += __shfl_xor_sync(0xFFFFFFFFu, acc[q], 8);
        acc[q] += __shfl_xor_sync(0xFFFFFFFFu, acc[q], 16);
    }

    if (grp == 0) {
        float di = g_dinv[w];
        float4 bb0 = __ldg((const float4*)b2 + l8 * 2);
        float4 bb1 = __ldg((const float4*)b2 + l8 * 2 + 1);
        float4 v0 = make_float4(fmaxf(di * acc[0] + bb0.x, 0.0f),
                                fmaxf(di * acc[1] + bb0.y, 0.0f),
                                fmaxf(di * acc[2] + bb0.z, 0.0f),
                                fmaxf(di * acc[3] + bb0.w, 0.0f));
        float4 v1 = make_float4(fmaxf(di * acc[4] + bb1.x, 0.0f),
                                fmaxf(di * acc[5] + bb1.y, 0.0f),
                                fmaxf(di * acc[6] + bb1.z, 0.0f),
                                fmaxf(di * acc[7] + bb1.w, 0.0f));
        int g = __ldg(batch + w);
        red_add_v4(&g_gsum[(g << 6) + l8 * 8],     v0);
        red_add_v4(&g_gsum[(g << 6) + l8 * 8 + 4], v1);
    }
}

// ---------------- mean -----------------------------------------------------
__global__ void k_final(float* __restrict__ out) {
    int i = blockIdx.x * blockDim.x + threadIdx.x;
    if (i < NG * 64) out[i] = g_gsum[i] / fmaxf(g_gcnt[i >> 6], 1.0f);
}

// ===========================================================================
extern "C" void kernel_launch(void* const* d_in, const int* in_sizes, int n_in,
                              void* d_out, int out_size) {
    const float* x     = (const float*)d_in[0];
    const int*   ei    = (const int*)d_in[1];
    const int*   batch = (const int*)d_in[2];
    const float* W1    = (const float*)d_in[3];
    const float* b1    = (const float*)d_in[4];
    const float* W2    = (const float*)d_in[5];
    const float* b2    = (const float*)d_in[6];
    float*       out   = (float*)d_out;

    const int N = in_sizes[2];        // 100000
    const int E = in_sizes[1] / 2;    // 1600000
    const int* src = ei;
    const int* dst = ei + E;

    const int TB = 256;
    int nb_N  = (N + TB - 1) / TB;
    int nb_E4 = ((E + 3) / 4 + TB - 1) / TB;
    int nb_sc = (N + 1023) / 1024;    // scan blocks

    // graph prep: degree, rowptr, csr, dinv, graph counts
    k_init   <<<nb_N, TB>>>(N);
    k_hist   <<<nb_E4, TB>>>(dst, E);
    k_scan1  <<<nb_sc, 1024>>>(N);
    k_scan2  <<<1, 32>>>(nb_sc);
    k_scan3  <<<nb_N, TB>>>(batch, N);
    k_scatter<<<nb_E4, TB>>>(src, dst, E);

    // layer 1
    k_gemm<1><<<(N + 127) / 128, TB>>>(x, W1, N);
    k_agg1   <<<(N * 32 + TB - 1) / TB, TB>>>(b1, N);

    // layer 2 + pool
    k_gemm<2><<<(N + 127) / 128, TB>>>(nullptr, W2, N);
    k_agg2   <<<(N * 32 + TB - 1) / TB, TB>>>(batch, b2, N);

    k_final<<<(NG * 64 + TB - 1) / TB, TB>>>(out);
}